// round 5
// baseline (speedup 1.0000x reference)
#include <cuda_runtime.h>
#include <cuda_bf16.h>
#include <cstdint>

// ---------------- problem constants ----------------
#define DD 32
#define MMODES 64
#define BB 16
#define NN 1024
#define FF 2080
#define FP 2176            // FF padded to 17*128
#define NROWT 17           // 128-row tiles
#define NPAIRQ 153         // 17*18/2 symmetric tile pairs

// ---------------- GEMM tiling ----------------
#define BM 128
#define BN 128
#define BKC 32             // K per chunk (bf16 -> 64B rows)
#define NCH 32             // NN / BKC
#define KS 2               // k16 steps per chunk
#define NSTAGE 3

// smem: 4 X planes (128x64B) + 4 Y planes (128x64B) per stage
#define XPL 8192
#define YOFF 32768                 // 4 * XPL
#define STAGE_BYTES 65536
#define SMEM_DYN (NSTAGE * STAGE_BYTES + 1024)   // 197632

// epilogue staging (reuses stage smem)
#define PITCH_T 272
#define PLANE_T 34816              // 128 * 272
#define PITCH_O 1040               // 128*8 + 16

// ---------------- device scratch (bf16 split planes) ----------------
__device__ __nv_bfloat16 gArh[(size_t)FP * NN];
__device__ __nv_bfloat16 gArl[(size_t)FP * NN];
__device__ __nv_bfloat16 gAih[(size_t)FP * NN];
__device__ __nv_bfloat16 gAil[(size_t)FP * NN];

__device__ __nv_bfloat16 gHrh[(size_t)BB * NN * NN];
__device__ __nv_bfloat16 gHrl[(size_t)BB * NN * NN];
__device__ __nv_bfloat16 gHih[(size_t)BB * NN * NN];
__device__ __nv_bfloat16 gHil[(size_t)BB * NN * NN];

__device__ __nv_bfloat16 gTrh[(size_t)BB * FP * NN];
__device__ __nv_bfloat16 gTrl[(size_t)BB * FP * NN];
__device__ __nv_bfloat16 gTih[(size_t)BB * FP * NN];
__device__ __nv_bfloat16 gTil[(size_t)BB * FP * NN];

// ---------------- helpers ----------------
__device__ __forceinline__ uint32_t smem_u32(const void* p) {
    uint32_t a;
    asm("{ .reg .u64 t; cvta.to.shared.u64 t, %1; cvt.u32.u64 %0, t; }" : "=r"(a) : "l"(p));
    return a;
}
#define SWZ64(off) ((off) ^ (((off) >> 3) & 0x30))

#define CPA16(dst, src) \
    asm volatile("cp.async.cg.shared.global [%0], [%1], 16;" :: "r"(dst), "l"(src))
#define CPA_COMMIT() asm volatile("cp.async.commit_group;" ::: "memory")
#define CPA_WAIT(n)  asm volatile("cp.async.wait_group %0;" :: "n"(n) : "memory")

__device__ __forceinline__ void ldsm4(uint32_t* r, uint32_t addr) {
    asm volatile("ldmatrix.sync.aligned.m8n8.x4.shared.b16 {%0,%1,%2,%3}, [%4];"
        : "=r"(r[0]), "=r"(r[1]), "=r"(r[2]), "=r"(r[3]) : "r"(addr));
}
__device__ __forceinline__ void mma16816(float* c, const uint32_t* a,
                                         uint32_t b0, uint32_t b1) {
    asm volatile(
        "mma.sync.aligned.m16n8k16.row.col.f32.bf16.bf16.f32 "
        "{%0,%1,%2,%3}, {%4,%5,%6,%7}, {%8,%9}, {%0,%1,%2,%3};"
        : "+f"(c[0]), "+f"(c[1]), "+f"(c[2]), "+f"(c[3])
        : "r"(a[0]), "r"(a[1]), "r"(a[2]), "r"(a[3]), "r"(b0), "r"(b1));
}
__device__ __forceinline__ void split2(float v, __nv_bfloat16& h, __nv_bfloat16& l) {
    h = __float2bfloat16_rn(v);
    l = __float2bfloat16_rn(v - __bfloat162float(h));
}

// ---------------------------------------------------------------------------
// Kernel 1: amplitudes -> 4 bf16 split planes (rows >= FF zeroed)
// ---------------------------------------------------------------------------
__global__ void amp_kernel(const float* __restrict__ U_re,
                           const float* __restrict__ U_im) {
    __shared__ float sUre[MMODES * MMODES];
    __shared__ float sUim[MMODES * MMODES];
    for (int t = threadIdx.x; t < MMODES * MMODES; t += blockDim.x) {
        sUre[t] = U_re[t];
        sUim[t] = U_im[t];
    }
    __syncthreads();

    int f = blockIdx.x;
    if (f >= FF) {
        __nv_bfloat16 z = __float2bfloat16(0.f);
        for (int i = threadIdx.x; i < NN; i += blockDim.x) {
            size_t o = (size_t)f * NN + i;
            gArh[o] = z; gArl[o] = z; gAih[o] = z; gAil[o] = z;
        }
        return;
    }
    int j = 0, rem = f;
    while (rem >= (MMODES - j)) { rem -= (MMODES - j); j++; }
    int k = j + rem;
    float scale = (j == k) ? 0.70710678118654752f : 1.0f;

    for (int i = threadIdx.x; i < NN; i += blockDim.x) {
        int x = i >> 5, y = i & 31;
        float are = sUre[j * MMODES + x],       aim = sUim[j * MMODES + x];
        float bre = sUre[k * MMODES + DD + y],  bim = sUim[k * MMODES + DD + y];
        float cre = sUre[k * MMODES + x],       cim = sUim[k * MMODES + x];
        float dre = sUre[j * MMODES + DD + y],  dim_ = sUim[j * MMODES + DD + y];
        float re = (are * bre - aim * bim + cre * dre - cim * dim_) * scale;
        float im = (are * bim + aim * bre + cre * dim_ + cim * dre) * scale;
        size_t o = (size_t)f * NN + i;
        __nv_bfloat16 h, l;
        split2(re, h, l); gArh[o] = h; gArl[o] = l;
        split2(im, h, l); gAih[o] = h; gAil[o] = l;
    }
}

// ---------------------------------------------------------------------------
// Kernel 2: Hermitian H build -> 4 bf16 split planes
// ---------------------------------------------------------------------------
#define HT 32
__global__ __launch_bounds__(256) void herm_kernel(const float* __restrict__ rho_re,
                                                   const float* __restrict__ rho_im) {
    int p = blockIdx.x, ti = 0;
    while (p >= (HT - ti)) { p -= (HT - ti); ti++; }
    int tj = ti + p;
    int b = blockIdx.y;

    __shared__ float sRe[HT][HT + 1];
    __shared__ float sIm[HT][HT + 1];

    size_t base = (size_t)b * NN * NN;
    int r0 = ti * HT, c0 = tj * HT;
    int t = threadIdx.x;

    #pragma unroll
    for (int it = 0; it < 4; it++) {
        int slot = it * 256 + t;
        int r = slot >> 5, c = slot & 31;
        size_t g = base + (size_t)(r0 + r) * NN + c0 + c;
        sRe[r][c] = rho_re[g];
        sIm[r][c] = rho_im[g];
    }
    __syncthreads();

    #pragma unroll
    for (int it = 0; it < 4; it++) {
        int slot = it * 256 + t;
        int r = slot >> 5, c = slot & 31;
        float vre, vim;
        if (ti < tj) { vre = sRe[r][c]; vim = sIm[r][c]; }
        else if (r < c) { vre = sRe[r][c]; vim = sIm[r][c]; }
        else if (r > c) { vre = sRe[c][r]; vim = -sIm[c][r]; }
        else { vre = sRe[r][c]; vim = 0.0f; }
        size_t o = base + (size_t)(r0 + r) * NN + c0 + c;
        __nv_bfloat16 h, l;
        split2(vre, h, l); gHrh[o] = h; gHrl[o] = l;
        split2(vim, h, l); gHih[o] = h; gHil[o] = l;
    }
    if (ti < tj) {
        #pragma unroll
        for (int it = 0; it < 4; it++) {
            int slot = it * 256 + t;
            int r = slot >> 5, c = slot & 31;
            float vre = sRe[c][r], vim = -sIm[c][r];
            size_t o = base + (size_t)(c0 + r) * NN + r0 + c;
            __nv_bfloat16 h, l;
            split2(vre, h, l); gHrh[o] = h; gHrl[o] = l;
            split2(vim, h, l); gHih[o] = h; gHil[o] = l;
        }
    }
}

// ---------------------------------------------------------------------------
// Unified split-bf16 complex GEMM, 128x128 tile:  C = X * conj(Y)^T
//   re = XrYr + XiYi ; im = XiYr - XrYi
// smem planes per side: 0=r_h 1=r_l 2=i_h 3=i_l
//   mode 0: X = Amp, Y = H rows   -> bf16-split T
//   mode 1: X = T,   Y = Amp      -> float2 out (+ conj mirror for tg>tf)
// ---------------------------------------------------------------------------
__global__ __launch_bounds__(256, 1) void gemm_kernel(int mode, float2* __restrict__ out) {
    extern __shared__ char dsm[];
    uint32_t sbraw = smem_u32(dsm);
    uint32_t sb = (sbraw + 1023u) & ~1023u;
    char* smem = dsm + (sb - sbraw);

    const int t = threadIdx.x;
    const int lane = t & 31;
    const int wid = t >> 5;
    const int wm = wid & 1;       // 2 warps along M (64 rows each)
    const int wn = wid >> 1;      // 4 warps along N (32 cols each)

    int b, f0, n0, tf = 0, tg = 0;
    const __nv_bfloat16 *Xp[4], *Yp[4];
    if (mode == 0) {
        b = blockIdx.z; f0 = blockIdx.y * BM; n0 = blockIdx.x * BN;
        size_t ab = (size_t)f0 * NN;
        Xp[0] = gArh + ab; Xp[1] = gArl + ab; Xp[2] = gAih + ab; Xp[3] = gAil + ab;
        size_t bbo = ((size_t)b * NN + n0) * NN;
        Yp[0] = gHrh + bbo; Yp[1] = gHrl + bbo; Yp[2] = gHih + bbo; Yp[3] = gHil + bbo;
    } else {
        b = blockIdx.y;
        int p = blockIdx.x;
        while (p >= (NROWT - tf)) { p -= (NROWT - tf); tf++; }
        tg = tf + p;
        f0 = tf * BM; n0 = tg * BN;
        size_t ab = ((size_t)b * FP + f0) * NN;
        Xp[0] = gTrh + ab; Xp[1] = gTrl + ab; Xp[2] = gTih + ab; Xp[3] = gTil + ab;
        size_t bbo = (size_t)n0 * NN;
        Yp[0] = gArh + bbo; Yp[1] = gArl + bbo; Yp[2] = gAih + bbo; Yp[3] = gAil + bbo;
    }

    // ---- prefetch: 16 cp.async per thread per stage ----
    auto prefetch = [&](uint32_t stOff, int k0) {
        #pragma unroll
        for (int it = 0; it < 8; it++) {             // X: 4*128*4 = 2048 chunks
            int slot = it * 256 + t;
            int v = slot >> 9;
            int rem = slot & 511;
            int row = rem >> 2, c16 = rem & 3;
            uint32_t dst = sb + stOff + v * XPL + SWZ64(row * 64 + c16 * 16);
            const char* src = (const char*)(Xp[v] + (size_t)row * NN + k0) + c16 * 16;
            CPA16(dst, src);
        }
        #pragma unroll
        for (int it = 0; it < 8; it++) {             // Y: 4*128*4 = 2048 chunks
            int slot = it * 256 + t;
            int v = slot >> 9;
            int rem = slot & 511;
            int row = rem >> 2, c16 = rem & 3;
            uint32_t dst = sb + stOff + YOFF + v * XPL + SWZ64(row * 64 + c16 * 16);
            const char* src = (const char*)(Yp[v] + (size_t)row * NN + k0) + c16 * 16;
            CPA16(dst, src);
        }
    };

    float accR[4][4][4], accI[4][4][4];
    #pragma unroll
    for (int mt = 0; mt < 4; mt++)
        #pragma unroll
        for (int nt = 0; nt < 4; nt++)
            #pragma unroll
            for (int q = 0; q < 4; q++) { accR[mt][nt][q] = 0.f; accI[mt][nt][q] = 0.f; }

    // per-lane ldmatrix addressing (64B rows, SW64)
    const int lrow = lane & 15;
    const uint32_t c16base = (uint32_t)(lane >> 4);
    uint32_t aOff[4], aXm[4], bOff[2], bXm[2];
    #pragma unroll
    for (int mt = 0; mt < 4; mt++) {
        int row = wm * 64 + mt * 16 + lrow;
        aOff[mt] = row * 64;
        aXm[mt] = (row >> 1) & 3;
    }
    #pragma unroll
    for (int pr = 0; pr < 2; pr++) {
        int row = wn * 32 + pr * 16 + lrow;
        bOff[pr] = row * 64;
        bXm[pr] = (row >> 1) & 3;
    }

    prefetch(0, 0);
    CPA_COMMIT();
    prefetch(STAGE_BYTES, BKC);
    CPA_COMMIT();

    for (int c = 0; c < NCH; c++) {
        CPA_WAIT(1);
        __syncthreads();
        if (c + 2 < NCH)
            prefetch(((c + 2) % NSTAGE) * STAGE_BYTES, (c + 2) * BKC);
        CPA_COMMIT();

        const uint32_t stBase = sb + (c % NSTAGE) * STAGE_BYTES;
        #pragma unroll
        for (int ks = 0; ks < KS; ks++) {
            const uint32_t c16 = (uint32_t)(ks * 2) + c16base;

            uint32_t Xh[4][4], Xl[4][4];
            // Y-pass using current X group
            auto ypass = [&](int ypA, float (&acc)[4][4][4], bool neg) {
                uint32_t Yh[2][4], Yl[2][4];
                #pragma unroll
                for (int pr = 0; pr < 2; pr++) {
                    ldsm4(Yh[pr], stBase + YOFF + ypA * XPL + bOff[pr] + ((c16 ^ bXm[pr]) << 4));
                    ldsm4(Yl[pr], stBase + YOFF + (ypA + 1) * XPL + bOff[pr] + ((c16 ^ bXm[pr]) << 4));
                }
                if (neg) {
                    #pragma unroll
                    for (int pr = 0; pr < 2; pr++)
                        #pragma unroll
                        for (int q = 0; q < 4; q++) {
                            Yh[pr][q] ^= 0x80008000u;
                            Yl[pr][q] ^= 0x80008000u;
                        }
                }
                #pragma unroll
                for (int mt = 0; mt < 4; mt++)
                    #pragma unroll
                    for (int nt = 0; nt < 4; nt++) {
                        const int pr = nt >> 1, hh = nt & 1;
                        float* cc = acc[mt][nt];
                        mma16816(cc, Xh[mt], Yh[pr][hh], Yh[pr][hh + 2]);
                        mma16816(cc, Xh[mt], Yl[pr][hh], Yl[pr][hh + 2]);
                        mma16816(cc, Xl[mt], Yh[pr][hh], Yh[pr][hh + 2]);
                    }
            };

            // group A: X = Xr (planes 0,1)
            #pragma unroll
            for (int mt = 0; mt < 4; mt++) {
                ldsm4(Xh[mt], stBase + 0 * XPL + aOff[mt] + ((c16 ^ aXm[mt]) << 4));
                ldsm4(Xl[mt], stBase + 1 * XPL + aOff[mt] + ((c16 ^ aXm[mt]) << 4));
            }
            ypass(0, accR, false);   // XrYr -> re
            ypass(2, accI, true);    // -XrYi -> im

            // group B: X = Xi (planes 2,3)
            #pragma unroll
            for (int mt = 0; mt < 4; mt++) {
                ldsm4(Xh[mt], stBase + 2 * XPL + aOff[mt] + ((c16 ^ aXm[mt]) << 4));
                ldsm4(Xl[mt], stBase + 3 * XPL + aOff[mt] + ((c16 ^ aXm[mt]) << 4));
            }
            ypass(2, accR, false);   // XiYi -> re
            ypass(0, accI, false);   // XiYr -> im
        }
    }
    __syncthreads();   // stage smem about to be reused for epilogue

    // ---- epilogue: stage in smem + coalesced writeback ----
    const int erow0 = wm * 64 + (lane >> 2);
    const int ecol0 = wn * 32 + (lane & 3) * 2;

    if (mode == 0) {
        #pragma unroll
        for (int mt = 0; mt < 4; mt++)
            #pragma unroll
            for (int nt = 0; nt < 4; nt++) {
                int col = ecol0 + nt * 8;
                #pragma unroll
                for (int hlf = 0; hlf < 2; hlf++) {
                    int row = erow0 + mt * 16 + hlf * 8;
                    float re0 = accR[mt][nt][hlf * 2 + 0], re1 = accR[mt][nt][hlf * 2 + 1];
                    float im0 = accI[mt][nt][hlf * 2 + 0], im1 = accI[mt][nt][hlf * 2 + 1];
                    __nv_bfloat16 h0, l0, h1, l1;
                    split2(re0, h0, l0); split2(re1, h1, l1);
                    *(__nv_bfloat162*)(smem + 0 * PLANE_T + row * PITCH_T + col * 2) =
                        __nv_bfloat162(h0, h1);
                    *(__nv_bfloat162*)(smem + 1 * PLANE_T + row * PITCH_T + col * 2) =
                        __nv_bfloat162(l0, l1);
                    split2(im0, h0, l0); split2(im1, h1, l1);
                    *(__nv_bfloat162*)(smem + 2 * PLANE_T + row * PITCH_T + col * 2) =
                        __nv_bfloat162(h0, h1);
                    *(__nv_bfloat162*)(smem + 3 * PLANE_T + row * PITCH_T + col * 2) =
                        __nv_bfloat162(l0, l1);
                }
            }
        __syncthreads();

        __nv_bfloat16* Td[4];
        size_t tb0 = ((size_t)b * FP + f0) * NN + n0;
        Td[0] = gTrh + tb0; Td[1] = gTrl + tb0; Td[2] = gTih + tb0; Td[3] = gTil + tb0;
        #pragma unroll
        for (int v = 0; v < 4; v++) {
            #pragma unroll
            for (int it = 0; it < 8; it++) {
                int slot = it * 256 + t;
                int row = slot >> 4, c16 = slot & 15;
                uint4 val = *(uint4*)(smem + v * PLANE_T + row * PITCH_T + c16 * 16);
                *(uint4*)(Td[v] + (size_t)row * NN + c16 * 8) = val;
            }
        }
    } else {
        #pragma unroll
        for (int mt = 0; mt < 4; mt++)
            #pragma unroll
            for (int nt = 0; nt < 4; nt++) {
                int col = ecol0 + nt * 8;
                #pragma unroll
                for (int hlf = 0; hlf < 2; hlf++) {
                    int row = erow0 + mt * 16 + hlf * 8;
                    float4 v4;
                    v4.x = accR[mt][nt][hlf * 2 + 0];
                    v4.y = accI[mt][nt][hlf * 2 + 0];
                    v4.z = accR[mt][nt][hlf * 2 + 1];
                    v4.w = accI[mt][nt][hlf * 2 + 1];
                    *(float4*)(smem + row * PITCH_O + col * 8) = v4;
                }
            }
        __syncthreads();

        const size_t obase = (size_t)b * FF;
        #pragma unroll 4
        for (int it = 0; it < 64; it++) {
            int slot = it * 256 + t;
            int row = slot >> 7, cc = slot & 127;
            int fr = f0 + row, gc = n0 + cc;
            if (fr < FF && gc < FF) {
                float2 v = *(float2*)(smem + row * PITCH_O + cc * 8);
                out[(obase + fr) * FF + gc] = v;
            }
        }
        if (tg > tf) {   // off-diagonal: mirror conj-transpose
            #pragma unroll 4
            for (int it = 0; it < 64; it++) {
                int slot = it * 256 + t;
                int g = slot >> 7, ff = slot & 127;
                int gr = n0 + g, fc = f0 + ff;
                if (gr < FF && fc < FF) {
                    float2 v = *(float2*)(smem + ff * PITCH_O + g * 8);
                    out[(obase + gr) * FF + fc] = make_float2(v.x, -v.y);
                }
            }
        }
    }
}

// ---------------------------------------------------------------------------
extern "C" void kernel_launch(void* const* d_in, const int* in_sizes, int n_in,
                              void* d_out, int out_size) {
    const float* rho_re = (const float*)d_in[0];
    const float* rho_im = (const float*)d_in[1];
    const float* U_re   = (const float*)d_in[2];
    const float* U_im   = (const float*)d_in[3];
    float2* out = (float2*)d_out;

    cudaFuncSetAttribute(gemm_kernel, cudaFuncAttributeMaxDynamicSharedMemorySize, SMEM_DYN);

    amp_kernel<<<FP, 256>>>(U_re, U_im);

    dim3 hg(HT * (HT + 1) / 2, BB);
    herm_kernel<<<hg, 256>>>(rho_re, rho_im);

    dim3 g1(NN / BN, NROWT, BB);
    gemm_kernel<<<g1, 256, SMEM_DYN>>>(0, nullptr);

    dim3 g2(NPAIRQ, BB);
    gemm_kernel<<<g2, 256, SMEM_DYN>>>(1, out);
}

// round 9
// speedup vs baseline: 1.5818x; 1.5818x over previous
#include <cuda_runtime.h>
#include <cuda_bf16.h>
#include <cstdint>

// ---------------- problem constants ----------------
#define DD 32
#define MMODES 64
#define BB 16
#define NN 1024
#define FF 2080
#define FP 2176            // FF padded to 17*128
#define NROWT 17           // f row tiles (BM=128)
#define NCOLT 33           // g col tiles (BN=64)
#define NPAIR2 289         // sum_{tf=0..16} (33-2*tf)

// ---------------- GEMM tiling ----------------
#define BM 128
#define BN 64
#define BKC 64             // K elements per chunk (fp32 -> 256B rows)
#define NCH 16             // NN / BKC
#define KS 8               // k8 steps per chunk

// smem: 2 X planes (128 x 256B) + 2 Y planes (64 x 256B) per stage
#define XPL 32768
#define YPL 16384
#define YOFF 65536                 // 2 * XPL
#define STAGE_BYTES 98304
#define SMEM_DYN (2 * STAGE_BYTES + 1024)   // 197632

// epilogue staging (reuses stage smem)
#define PITCH_T 272                // 64 fp32 + pad
#define PLANE_T 34816              // 128 * 272
#define PITCH_O 528

// ---------------- device scratch (tf32-rounded fp32 planes) ----------------
__device__ float gAr[(size_t)FP * NN];
__device__ float gAi[(size_t)FP * NN];
__device__ float gHr[(size_t)BB * NN * NN];
__device__ float gHi[(size_t)BB * NN * NN];
__device__ float gTr[(size_t)BB * FP * NN];
__device__ float gTi[(size_t)BB * FP * NN];

// ---------------- helpers ----------------
__device__ __forceinline__ uint32_t smem_u32(const void* p) {
    uint32_t a;
    asm("{ .reg .u64 t; cvta.to.shared.u64 t, %1; cvt.u32.u64 %0, t; }" : "=r"(a) : "l"(p));
    return a;
}
__device__ __forceinline__ float to_tf32(float v) {
    uint32_t r;
    asm("cvt.rna.tf32.f32 %0, %1;" : "=r"(r) : "f"(v));
    return __uint_as_float(r);
}
// 256B rows, 16B groups: group' = c ^ (row & 7) -> conflict-free ldsm
#define SWZOFF(row, c) ((row) * 256 + (((c) ^ ((row) & 7)) << 4))

#define CPA16(dst, src) \
    asm volatile("cp.async.cg.shared.global [%0], [%1], 16;" :: "r"(dst), "l"(src))
#define CPA_COMMIT() asm volatile("cp.async.commit_group;" ::: "memory")
#define CPA_WAIT(n)  asm volatile("cp.async.wait_group %0;" :: "n"(n) : "memory")

__device__ __forceinline__ void ldsm4(uint32_t* r, uint32_t addr) {
    asm volatile("ldmatrix.sync.aligned.m8n8.x4.shared.b16 {%0,%1,%2,%3}, [%4];"
        : "=r"(r[0]), "=r"(r[1]), "=r"(r[2]), "=r"(r[3]) : "r"(addr));
}
__device__ __forceinline__ void mma_tf32(float* c, const uint32_t* a,
                                         uint32_t b0, uint32_t b1) {
    asm volatile(
        "mma.sync.aligned.m16n8k8.row.col.f32.tf32.tf32.f32 "
        "{%0,%1,%2,%3}, {%4,%5,%6,%7}, {%8,%9}, {%0,%1,%2,%3};"
        : "+f"(c[0]), "+f"(c[1]), "+f"(c[2]), "+f"(c[3])
        : "r"(a[0]), "r"(a[1]), "r"(a[2]), "r"(a[3]), "r"(b0), "r"(b1));
}

// ---------------------------------------------------------------------------
// Kernel 1: amplitudes -> tf32-rounded fp32 planes (rows >= FF zeroed)
// ---------------------------------------------------------------------------
__global__ void amp_kernel(const float* __restrict__ U_re,
                           const float* __restrict__ U_im) {
    __shared__ float sUre[MMODES * MMODES];
    __shared__ float sUim[MMODES * MMODES];
    for (int t = threadIdx.x; t < MMODES * MMODES; t += blockDim.x) {
        sUre[t] = U_re[t];
        sUim[t] = U_im[t];
    }
    __syncthreads();

    int f = blockIdx.x;
    if (f >= FF) {
        for (int i = threadIdx.x; i < NN; i += blockDim.x) {
            size_t o = (size_t)f * NN + i;
            gAr[o] = 0.f; gAi[o] = 0.f;
        }
        return;
    }
    int j = 0, rem = f;
    while (rem >= (MMODES - j)) { rem -= (MMODES - j); j++; }
    int k = j + rem;
    float scale = (j == k) ? 0.70710678118654752f : 1.0f;

    for (int i = threadIdx.x; i < NN; i += blockDim.x) {
        int x = i >> 5, y = i & 31;
        float are = sUre[j * MMODES + x],       aim = sUim[j * MMODES + x];
        float bre = sUre[k * MMODES + DD + y],  bim = sUim[k * MMODES + DD + y];
        float cre = sUre[k * MMODES + x],       cim = sUim[k * MMODES + x];
        float dre = sUre[j * MMODES + DD + y],  dim_ = sUim[j * MMODES + DD + y];
        float re = (are * bre - aim * bim + cre * dre - cim * dim_) * scale;
        float im = (are * bim + aim * bre + cre * dim_ + cim * dre) * scale;
        size_t o = (size_t)f * NN + i;
        gAr[o] = to_tf32(re);
        gAi[o] = to_tf32(im);
    }
}

// ---------------------------------------------------------------------------
// Kernel 2: Hermitian H build -> tf32-rounded fp32 planes
// ---------------------------------------------------------------------------
#define HT 32
__global__ __launch_bounds__(256) void herm_kernel(const float* __restrict__ rho_re,
                                                   const float* __restrict__ rho_im) {
    int p = blockIdx.x, ti = 0;
    while (p >= (HT - ti)) { p -= (HT - ti); ti++; }
    int tj = ti + p;
    int b = blockIdx.y;

    __shared__ float sRe[HT][HT + 1];
    __shared__ float sIm[HT][HT + 1];

    size_t base = (size_t)b * NN * NN;
    int r0 = ti * HT, c0 = tj * HT;
    int t = threadIdx.x;

    #pragma unroll
    for (int it = 0; it < 4; it++) {
        int slot = it * 256 + t;
        int r = slot >> 5, c = slot & 31;
        size_t g = base + (size_t)(r0 + r) * NN + c0 + c;
        sRe[r][c] = rho_re[g];
        sIm[r][c] = rho_im[g];
    }
    __syncthreads();

    #pragma unroll
    for (int it = 0; it < 4; it++) {
        int slot = it * 256 + t;
        int r = slot >> 5, c = slot & 31;
        float vre, vim;
        if (ti < tj) { vre = sRe[r][c]; vim = sIm[r][c]; }
        else if (r < c) { vre = sRe[r][c]; vim = sIm[r][c]; }
        else if (r > c) { vre = sRe[c][r]; vim = -sIm[c][r]; }
        else { vre = sRe[r][c]; vim = 0.0f; }
        size_t o = base + (size_t)(r0 + r) * NN + c0 + c;
        gHr[o] = to_tf32(vre);
        gHi[o] = to_tf32(vim);
    }
    if (ti < tj) {
        #pragma unroll
        for (int it = 0; it < 4; it++) {
            int slot = it * 256 + t;
            int r = slot >> 5, c = slot & 31;
            float vre = sRe[c][r], vim = -sIm[c][r];
            size_t o = base + (size_t)(c0 + r) * NN + r0 + c;
            gHr[o] = to_tf32(vre);
            gHi[o] = to_tf32(vim);
        }
    }
}

// ---------------------------------------------------------------------------
// Unified tf32 complex GEMM, 128x64 tile:  C = X * conj(Y)^T
//   re = XrYr + XiYi ; im = XiYr - XrYi  (Yi sign-flipped via fp32 XOR)
//   mode 0: X = Amp, Y = H rows   -> tf32-rounded fp32 T planes
//   mode 1: X = T,   Y = Amp      -> float2 out (+ conj mirror, tg>=2tf+2)
// ---------------------------------------------------------------------------
__global__ __launch_bounds__(256, 1) void gemm_kernel(int mode, float2* __restrict__ out) {
    extern __shared__ char dsm[];
    uint32_t sbraw = smem_u32(dsm);
    uint32_t sb = (sbraw + 1023u) & ~1023u;
    char* smem = dsm + (sb - sbraw);

    const int t = threadIdx.x;
    const int lane = t & 31;
    const int wid = t >> 5;
    const int wm = wid & 3;       // 4 warps along M (32 rows each)
    const int wn = wid >> 2;      // 2 warps along N (32 cols each)

    int b, f0, n0, tf = 0, tg = 0;
    const float *Xp[2], *Yp[2];
    if (mode == 0) {
        b = blockIdx.z; f0 = blockIdx.y * BM; n0 = blockIdx.x * BN;
        size_t ab = (size_t)f0 * NN;
        Xp[0] = gAr + ab; Xp[1] = gAi + ab;
        size_t bbo = ((size_t)b * NN + n0) * NN;
        Yp[0] = gHr + bbo; Yp[1] = gHi + bbo;
    } else {
        b = blockIdx.y;
        int p = blockIdx.x;
        while (p >= (NCOLT - 2 * tf)) { p -= (NCOLT - 2 * tf); tf++; }
        tg = 2 * tf + p;
        f0 = tf * BM; n0 = tg * BN;
        size_t ab = ((size_t)b * FP + f0) * NN;
        Xp[0] = gTr + ab; Xp[1] = gTi + ab;
        size_t bbo = (size_t)n0 * NN;
        Yp[0] = gAr + bbo; Yp[1] = gAi + bbo;
    }

    // ---- prefetch: 24 cp.async per thread per stage ----
    auto prefetch = [&](uint32_t stOff, int k0) {
        #pragma unroll
        for (int it = 0; it < 16; it++) {            // X: 2*128*16 = 4096 chunks
            int slot = it * 256 + t;
            int v = slot >> 11;
            int rem = slot & 2047;
            int row = rem >> 4, c = rem & 15;
            uint32_t dst = sb + stOff + v * XPL + SWZOFF(row, c);
            const char* src = (const char*)(Xp[v] + (size_t)row * NN + k0 + c * 4);
            CPA16(dst, src);
        }
        #pragma unroll
        for (int it = 0; it < 8; it++) {             // Y: 2*64*16 = 2048 chunks
            int slot = it * 256 + t;
            int v = slot >> 10;
            int rem = slot & 1023;
            int row = rem >> 4, c = rem & 15;
            uint32_t dst = sb + stOff + YOFF + v * YPL + SWZOFF(row, c);
            const char* src = (const char*)(Yp[v] + (size_t)row * NN + k0 + c * 4);
            CPA16(dst, src);
        }
    };

    float accR[2][4][4], accI[2][4][4];
    #pragma unroll
    for (int mt = 0; mt < 2; mt++)
        #pragma unroll
        for (int nt = 0; nt < 4; nt++)
            #pragma unroll
            for (int q = 0; q < 4; q++) { accR[mt][nt][q] = 0.f; accI[mt][nt][q] = 0.f; }

    // per-lane ldsm addressing: row base + 16B group (ks*2 + gsel) ^ (row&7)
    const uint32_t gsel = (uint32_t)(lane >> 4);
    uint32_t aRB[2], aSw[2], bRB[2], bSw[2];
    #pragma unroll
    for (int mt = 0; mt < 2; mt++) {
        int row = wm * 32 + mt * 16 + (lane & 15);
        aRB[mt] = row * 256;
        aSw[mt] = row & 7;
    }
    #pragma unroll
    for (int pr = 0; pr < 2; pr++) {
        int row = wn * 32 + pr * 16 + (lane & 15);
        bRB[pr] = row * 256;
        bSw[pr] = row & 7;
    }

    prefetch(0, 0);
    CPA_COMMIT();

    for (int c = 0; c < NCH; c++) {
        if (c + 1 < NCH) {
            prefetch(((c + 1) & 1) * STAGE_BYTES, (c + 1) * BKC);
            CPA_COMMIT();
            CPA_WAIT(1);
        } else {
            CPA_WAIT(0);
        }
        __syncthreads();

        const uint32_t stBase = sb + (c & 1) * STAGE_BYTES;

        #pragma unroll
        for (int ks = 0; ks < KS; ks++) {
            const uint32_t g0 = (uint32_t)(ks * 2) + gsel;

            uint32_t Ar[2][4], Ai[2][4];
            #pragma unroll
            for (int mt = 0; mt < 2; mt++) {
                uint32_t off = aRB[mt] + ((g0 ^ aSw[mt]) << 4);
                ldsm4(Ar[mt], stBase + 0 * XPL + off);
                ldsm4(Ai[mt], stBase + 1 * XPL + off);
            }
            uint32_t Br[2][4], Bi[2][4];
            #pragma unroll
            for (int pr = 0; pr < 2; pr++) {
                uint32_t off = bRB[pr] + ((g0 ^ bSw[pr]) << 4);
                ldsm4(Br[pr], stBase + YOFF + 0 * YPL + off);
                ldsm4(Bi[pr], stBase + YOFF + 1 * YPL + off);
            }
            uint32_t nBi[2][4];
            #pragma unroll
            for (int pr = 0; pr < 2; pr++)
                #pragma unroll
                for (int q = 0; q < 4; q++)
                    nBi[pr][q] = Bi[pr][q] ^ 0x80000000u;

            #pragma unroll
            for (int mt = 0; mt < 2; mt++)
                #pragma unroll
                for (int nt = 0; nt < 4; nt++) {
                    const int pr = nt >> 1, hh = nt & 1;
                    float* cr = accR[mt][nt];
                    float* ci = accI[mt][nt];
                    mma_tf32(cr, Ar[mt], Br[pr][hh],  Br[pr][hh + 2]);   // XrYr
                    mma_tf32(cr, Ai[mt], Bi[pr][hh],  Bi[pr][hh + 2]);   // XiYi
                    mma_tf32(ci, Ai[mt], Br[pr][hh],  Br[pr][hh + 2]);   // XiYr
                    mma_tf32(ci, Ar[mt], nBi[pr][hh], nBi[pr][hh + 2]);  // -XrYi
                }
        }
        __syncthreads();
    }

    // ---- epilogue ----
    const int erow0 = wm * 32 + (lane >> 2);
    const int ecol0 = wn * 32 + (lane & 3) * 2;

    if (mode == 0) {
        #pragma unroll
        for (int mt = 0; mt < 2; mt++)
            #pragma unroll
            for (int nt = 0; nt < 4; nt++) {
                int col = ecol0 + nt * 8;
                #pragma unroll
                for (int hlf = 0; hlf < 2; hlf++) {
                    int row = erow0 + mt * 16 + hlf * 8;
                    float2 vr, vi;
                    vr.x = to_tf32(accR[mt][nt][hlf * 2 + 0]);
                    vr.y = to_tf32(accR[mt][nt][hlf * 2 + 1]);
                    vi.x = to_tf32(accI[mt][nt][hlf * 2 + 0]);
                    vi.y = to_tf32(accI[mt][nt][hlf * 2 + 1]);
                    *(float2*)(smem + 0 * PLANE_T + row * PITCH_T + col * 4) = vr;
                    *(float2*)(smem + 1 * PLANE_T + row * PITCH_T + col * 4) = vi;
                }
            }
        __syncthreads();

        float* Td[2];
        size_t tb0 = ((size_t)b * FP + f0) * NN + n0;
        Td[0] = gTr + tb0; Td[1] = gTi + tb0;
        #pragma unroll
        for (int v = 0; v < 2; v++) {
            #pragma unroll
            for (int it = 0; it < 8; it++) {
                int slot = it * 256 + t;
                int row = slot >> 4, c4 = slot & 15;
                uint4 val = *(uint4*)(smem + v * PLANE_T + row * PITCH_T + c4 * 16);
                *(uint4*)(Td[v] + (size_t)row * NN + c4 * 4) = val;
            }
        }
    } else {
        #pragma unroll
        for (int mt = 0; mt < 2; mt++)
            #pragma unroll
            for (int nt = 0; nt < 4; nt++) {
                int col = ecol0 + nt * 8;
                #pragma unroll
                for (int hlf = 0; hlf < 2; hlf++) {
                    int row = erow0 + mt * 16 + hlf * 8;
                    float4 v4;
                    v4.x = accR[mt][nt][hlf * 2 + 0];
                    v4.y = accI[mt][nt][hlf * 2 + 0];
                    v4.z = accR[mt][nt][hlf * 2 + 1];
                    v4.w = accI[mt][nt][hlf * 2 + 1];
                    *(float4*)(smem + row * PITCH_O + col * 8) = v4;
                }
            }
        __syncthreads();

        const size_t obase = (size_t)b * FF;
        #pragma unroll 4
        for (int it = 0; it < 32; it++) {
            int slot = it * 256 + t;
            int row = slot >> 6, cc = slot & 63;
            int fr = f0 + row, gc = n0 + cc;
            if (fr < FF && gc < FF) {
                float2 v = *(float2*)(smem + row * PITCH_O + cc * 8);
                out[(obase + fr) * FF + gc] = v;
            }
        }
        if (tg >= 2 * tf + 2) {   // off-band: mirror conj-transpose
            #pragma unroll 4
            for (int it = 0; it < 32; it++) {
                int slot = it * 256 + t;
                int g = slot >> 7, ff = slot & 127;
                int gr = n0 + g, fc = f0 + ff;
                if (gr < FF && fc < FF) {
                    float2 v = *(float2*)(smem + ff * PITCH_O + g * 8);
                    out[(obase + gr) * FF + fc] = make_float2(v.x, -v.y);
                }
            }
        }
    }
}

// ---------------------------------------------------------------------------
extern "C" void kernel_launch(void* const* d_in, const int* in_sizes, int n_in,
                              void* d_out, int out_size) {
    const float* rho_re = (const float*)d_in[0];
    const float* rho_im = (const float*)d_in[1];
    const float* U_re   = (const float*)d_in[2];
    const float* U_im   = (const float*)d_in[3];
    float2* out = (float2*)d_out;

    cudaFuncSetAttribute(gemm_kernel, cudaFuncAttributeMaxDynamicSharedMemorySize, SMEM_DYN);

    amp_kernel<<<FP, 256>>>(U_re, U_im);

    dim3 hg(HT * (HT + 1) / 2, BB);
    herm_kernel<<<hg, 256>>>(rho_re, rho_im);

    dim3 g1(NN / BN, NROWT, BB);
    gemm_kernel<<<g1, 256, SMEM_DYN>>>(0, nullptr);

    dim3 g2(NPAIR2, BB);
    gemm_kernel<<<g2, 256, SMEM_DYN>>>(1, out);
}

// round 10
// speedup vs baseline: 1.7183x; 1.0863x over previous
#include <cuda_runtime.h>
#include <cuda_bf16.h>
#include <cstdint>

// ---------------- problem constants ----------------
#define DD 32
#define MMODES 64
#define BB 16
#define NN 1024
#define FF 2080
#define FP 2176            // FF padded to 17*128
#define NROWT 17           // f row tiles (BM=128)
#define NCOLT 33           // g col tiles (BN=64)
#define NPAIR2 289         // sum_{tf=0..16} (33-2*tf)

// ---------------- GEMM tiling ----------------
#define BM 128
#define BN 64
#define BKC 64             // K elements per chunk (fp32 -> 256B rows)
#define NCH 16             // NN / BKC
#define KS 8               // k8 steps per chunk

// smem: 2 X planes (128 x 256B) + 2 Y planes (64 x 256B) per stage
#define XPL 32768
#define YPL 16384
#define YOFF 65536                 // 2 * XPL
#define STAGE_BYTES 98304
#define SMEM_DYN (2 * STAGE_BYTES + 1024)   // 197632

// epilogue staging (reuses stage smem)
#define PITCH_T 272                // 64 fp32 + pad
#define PLANE_T 34816              // 128 * 272
#define PITCH_O 528

// ---------------- device scratch (tf32-rounded fp32 planes) ----------------
__device__ float gAr[(size_t)FP * NN];
__device__ float gAi[(size_t)FP * NN];
__device__ float gHr[(size_t)BB * NN * NN];
__device__ float gHi[(size_t)BB * NN * NN];
__device__ float gTr[(size_t)BB * FP * NN];
__device__ float gTi[(size_t)BB * FP * NN];

// ---------------- helpers ----------------
__device__ __forceinline__ uint32_t smem_u32(const void* p) {
    uint32_t a;
    asm("{ .reg .u64 t; cvta.to.shared.u64 t, %1; cvt.u32.u64 %0, t; }" : "=r"(a) : "l"(p));
    return a;
}
__device__ __forceinline__ float to_tf32(float v) {
    uint32_t r;
    asm("cvt.rna.tf32.f32 %0, %1;" : "=r"(r) : "f"(v));
    return __uint_as_float(r);
}
// 256B rows, 16B groups: group' = c ^ (row & 7) -> conflict-free ldsm
#define SWZOFF(row, c) ((row) * 256 + (((c) ^ ((row) & 7)) << 4))

#define CPA16(dst, src) \
    asm volatile("cp.async.cg.shared.global [%0], [%1], 16;" :: "r"(dst), "l"(src))
#define CPA_COMMIT() asm volatile("cp.async.commit_group;" ::: "memory")
#define CPA_WAIT(n)  asm volatile("cp.async.wait_group %0;" :: "n"(n) : "memory")

__device__ __forceinline__ void ldsm4(uint32_t* r, uint32_t addr) {
    asm volatile("ldmatrix.sync.aligned.m8n8.x4.shared.b16 {%0,%1,%2,%3}, [%4];"
        : "=r"(r[0]), "=r"(r[1]), "=r"(r[2]), "=r"(r[3]) : "r"(addr));
}
__device__ __forceinline__ void mma_tf32(float* c, const uint32_t* a,
                                         uint32_t b0, uint32_t b1) {
    asm volatile(
        "mma.sync.aligned.m16n8k8.row.col.f32.tf32.tf32.f32 "
        "{%0,%1,%2,%3}, {%4,%5,%6,%7}, {%8,%9}, {%0,%1,%2,%3};"
        : "+f"(c[0]), "+f"(c[1]), "+f"(c[2]), "+f"(c[3])
        : "r"(a[0]), "r"(a[1]), "r"(a[2]), "r"(a[3]), "r"(b0), "r"(b1));
}

// ---------------------------------------------------------------------------
// Kernel 1: amplitudes -> tf32-rounded fp32 planes (rows >= FF zeroed)
// ---------------------------------------------------------------------------
__global__ void amp_kernel(const float* __restrict__ U_re,
                           const float* __restrict__ U_im) {
    __shared__ float sUre[MMODES * MMODES];
    __shared__ float sUim[MMODES * MMODES];
    for (int t = threadIdx.x; t < MMODES * MMODES; t += blockDim.x) {
        sUre[t] = U_re[t];
        sUim[t] = U_im[t];
    }
    __syncthreads();

    int f = blockIdx.x;
    if (f >= FF) {
        for (int i = threadIdx.x; i < NN; i += blockDim.x) {
            size_t o = (size_t)f * NN + i;
            gAr[o] = 0.f; gAi[o] = 0.f;
        }
        return;
    }
    int j = 0, rem = f;
    while (rem >= (MMODES - j)) { rem -= (MMODES - j); j++; }
    int k = j + rem;
    float scale = (j == k) ? 0.70710678118654752f : 1.0f;

    for (int i = threadIdx.x; i < NN; i += blockDim.x) {
        int x = i >> 5, y = i & 31;
        float are = sUre[j * MMODES + x],       aim = sUim[j * MMODES + x];
        float bre = sUre[k * MMODES + DD + y],  bim = sUim[k * MMODES + DD + y];
        float cre = sUre[k * MMODES + x],       cim = sUim[k * MMODES + x];
        float dre = sUre[j * MMODES + DD + y],  dim_ = sUim[j * MMODES + DD + y];
        float re = (are * bre - aim * bim + cre * dre - cim * dim_) * scale;
        float im = (are * bim + aim * bre + cre * dim_ + cim * dre) * scale;
        size_t o = (size_t)f * NN + i;
        gAr[o] = to_tf32(re);
        gAi[o] = to_tf32(im);
    }
}

// ---------------------------------------------------------------------------
// Kernel 2: Hermitian H build -> tf32-rounded fp32 planes
// ---------------------------------------------------------------------------
#define HT 32
__global__ __launch_bounds__(256) void herm_kernel(const float* __restrict__ rho_re,
                                                   const float* __restrict__ rho_im) {
    int p = blockIdx.x, ti = 0;
    while (p >= (HT - ti)) { p -= (HT - ti); ti++; }
    int tj = ti + p;
    int b = blockIdx.y;

    __shared__ float sRe[HT][HT + 1];
    __shared__ float sIm[HT][HT + 1];

    size_t base = (size_t)b * NN * NN;
    int r0 = ti * HT, c0 = tj * HT;
    int t = threadIdx.x;

    #pragma unroll
    for (int it = 0; it < 4; it++) {
        int slot = it * 256 + t;
        int r = slot >> 5, c = slot & 31;
        size_t g = base + (size_t)(r0 + r) * NN + c0 + c;
        sRe[r][c] = rho_re[g];
        sIm[r][c] = rho_im[g];
    }
    __syncthreads();

    #pragma unroll
    for (int it = 0; it < 4; it++) {
        int slot = it * 256 + t;
        int r = slot >> 5, c = slot & 31;
        float vre, vim;
        if (ti < tj) { vre = sRe[r][c]; vim = sIm[r][c]; }
        else if (r < c) { vre = sRe[r][c]; vim = sIm[r][c]; }
        else if (r > c) { vre = sRe[c][r]; vim = -sIm[c][r]; }
        else { vre = sRe[r][c]; vim = 0.0f; }
        size_t o = base + (size_t)(r0 + r) * NN + c0 + c;
        gHr[o] = to_tf32(vre);
        gHi[o] = to_tf32(vim);
    }
    if (ti < tj) {
        #pragma unroll
        for (int it = 0; it < 4; it++) {
            int slot = it * 256 + t;
            int r = slot >> 5, c = slot & 31;
            float vre = sRe[c][r], vim = -sIm[c][r];
            size_t o = base + (size_t)(c0 + r) * NN + r0 + c;
            gHr[o] = to_tf32(vre);
            gHi[o] = to_tf32(vim);
        }
    }
}

// ---------------------------------------------------------------------------
// Unified tf32 complex GEMM, 128x64 tile:  C = X * conj(Y)^T
//   re = XrYr + XiYi ; im = XiYr - XrYi  (Yi sign-flipped via fp32 XOR)
// Prefetch for the next chunk is interleaved into the k-step loop (3 cp.async
// per thread per ks) so LDGSTS issue hides under the MMA stream instead of
// bursting at chunk boundaries.
//   mode 0: X = Amp, Y = H rows   -> tf32-rounded fp32 T planes
//   mode 1: X = T,   Y = Amp      -> float2 out (+ conj mirror, tg>=2tf+2)
// ---------------------------------------------------------------------------
__global__ __launch_bounds__(256, 1) void gemm_kernel(int mode, float2* __restrict__ out) {
    extern __shared__ char dsm[];
    uint32_t sbraw = smem_u32(dsm);
    uint32_t sb = (sbraw + 1023u) & ~1023u;
    char* smem = dsm + (sb - sbraw);

    const int t = threadIdx.x;
    const int lane = t & 31;
    const int wid = t >> 5;
    const int wm = wid & 3;       // 4 warps along M (32 rows each)
    const int wn = wid >> 2;      // 2 warps along N (32 cols each)

    int b, f0, n0, tf = 0, tg = 0;
    const float *Xp[2], *Yp[2];
    if (mode == 0) {
        b = blockIdx.z; f0 = blockIdx.y * BM; n0 = blockIdx.x * BN;
        size_t ab = (size_t)f0 * NN;
        Xp[0] = gAr + ab; Xp[1] = gAi + ab;
        size_t bbo = ((size_t)b * NN + n0) * NN;
        Yp[0] = gHr + bbo; Yp[1] = gHi + bbo;
    } else {
        b = blockIdx.y;
        int p = blockIdx.x;
        while (p >= (NCOLT - 2 * tf)) { p -= (NCOLT - 2 * tf); tf++; }
        tg = 2 * tf + p;
        f0 = tf * BM; n0 = tg * BN;
        size_t ab = ((size_t)b * FP + f0) * NN;
        Xp[0] = gTr + ab; Xp[1] = gTi + ab;
        size_t bbo = (size_t)n0 * NN;
        Yp[0] = gAr + bbo; Yp[1] = gAi + bbo;
    }

    // ---- full prefetch (prologue only): 24 cp.async per thread ----
    auto prefetch = [&](uint32_t stOff, int k0) {
        #pragma unroll
        for (int it = 0; it < 16; it++) {            // X: 2*128*16 = 4096 chunks
            int slot = it * 256 + t;
            int v = slot >> 11;
            int rem = slot & 2047;
            int row = rem >> 4, c = rem & 15;
            uint32_t dst = sb + stOff + v * XPL + SWZOFF(row, c);
            const char* src = (const char*)(Xp[v] + (size_t)row * NN + k0 + c * 4);
            CPA16(dst, src);
        }
        #pragma unroll
        for (int it = 0; it < 8; it++) {             // Y: 2*64*16 = 2048 chunks
            int slot = it * 256 + t;
            int v = slot >> 10;
            int rem = slot & 1023;
            int row = rem >> 4, c = rem & 15;
            uint32_t dst = sb + stOff + YOFF + v * YPL + SWZOFF(row, c);
            const char* src = (const char*)(Yp[v] + (size_t)row * NN + k0 + c * 4);
            CPA16(dst, src);
        }
    };

    // ---- per-ks prefetch slice: slots [ks*768, ks*768+768) of 6144 ----
    auto prefetch_slice = [&](uint32_t stOff, int k0, int ks) {
        #pragma unroll
        for (int q = 0; q < 3; q++) {
            int slot = ks * 768 + q * 256 + t;
            if (slot < 4096) {                       // X half
                int v = slot >> 11;
                int rem = slot & 2047;
                int row = rem >> 4, c = rem & 15;
                uint32_t dst = sb + stOff + v * XPL + SWZOFF(row, c);
                const char* src = (const char*)(Xp[v] + (size_t)row * NN + k0 + c * 4);
                CPA16(dst, src);
            } else {                                 // Y half
                int s2 = slot - 4096;
                int v = s2 >> 10;
                int rem = s2 & 1023;
                int row = rem >> 4, c = rem & 15;
                uint32_t dst = sb + stOff + YOFF + v * YPL + SWZOFF(row, c);
                const char* src = (const char*)(Yp[v] + (size_t)row * NN + k0 + c * 4);
                CPA16(dst, src);
            }
        }
    };

    float accR[2][4][4], accI[2][4][4];
    #pragma unroll
    for (int mt = 0; mt < 2; mt++)
        #pragma unroll
        for (int nt = 0; nt < 4; nt++)
            #pragma unroll
            for (int q = 0; q < 4; q++) { accR[mt][nt][q] = 0.f; accI[mt][nt][q] = 0.f; }

    // per-lane ldsm addressing: row base + 16B group (ks*2 + gsel) ^ (row&7)
    const uint32_t gsel = (uint32_t)(lane >> 4);
    uint32_t aRB[2], aSw[2], bRB[2], bSw[2];
    #pragma unroll
    for (int mt = 0; mt < 2; mt++) {
        int row = wm * 32 + mt * 16 + (lane & 15);
        aRB[mt] = row * 256;
        aSw[mt] = row & 7;
    }
    #pragma unroll
    for (int pr = 0; pr < 2; pr++) {
        int row = wn * 32 + pr * 16 + (lane & 15);
        bRB[pr] = row * 256;
        bSw[pr] = row & 7;
    }

    prefetch(0, 0);
    CPA_COMMIT();

    for (int c = 0; c < NCH; c++) {
        CPA_WAIT(0);          // drain the single in-flight group (this chunk's data)
        __syncthreads();

        const uint32_t stBase = sb + (c & 1) * STAGE_BYTES;
        const bool pf = (c + 1 < NCH);
        const uint32_t nstOff = ((c + 1) & 1) * STAGE_BYTES;
        const int nk0 = (c + 1) * BKC;

        #pragma unroll
        for (int ks = 0; ks < KS; ks++) {
            if (pf) prefetch_slice(nstOff, nk0, ks);

            const uint32_t g0 = (uint32_t)(ks * 2) + gsel;

            uint32_t Ar[2][4], Ai[2][4];
            #pragma unroll
            for (int mt = 0; mt < 2; mt++) {
                uint32_t off = aRB[mt] + ((g0 ^ aSw[mt]) << 4);
                ldsm4(Ar[mt], stBase + 0 * XPL + off);
                ldsm4(Ai[mt], stBase + 1 * XPL + off);
            }
            uint32_t Br[2][4], Bi[2][4];
            #pragma unroll
            for (int pr = 0; pr < 2; pr++) {
                uint32_t off = bRB[pr] + ((g0 ^ bSw[pr]) << 4);
                ldsm4(Br[pr], stBase + YOFF + 0 * YPL + off);
                ldsm4(Bi[pr], stBase + YOFF + 1 * YPL + off);
            }
            uint32_t nBi[2][4];
            #pragma unroll
            for (int pr = 0; pr < 2; pr++)
                #pragma unroll
                for (int q = 0; q < 4; q++)
                    nBi[pr][q] = Bi[pr][q] ^ 0x80000000u;

            #pragma unroll
            for (int mt = 0; mt < 2; mt++)
                #pragma unroll
                for (int nt = 0; nt < 4; nt++) {
                    const int pr = nt >> 1, hh = nt & 1;
                    float* cr = accR[mt][nt];
                    float* ci = accI[mt][nt];
                    mma_tf32(cr, Ar[mt], Br[pr][hh],  Br[pr][hh + 2]);   // XrYr
                    mma_tf32(cr, Ai[mt], Bi[pr][hh],  Bi[pr][hh + 2]);   // XiYi
                    mma_tf32(ci, Ai[mt], Br[pr][hh],  Br[pr][hh + 2]);   // XiYr
                    mma_tf32(ci, Ar[mt], nBi[pr][hh], nBi[pr][hh + 2]);  // -XrYi
                }
        }
        CPA_COMMIT();         // group for chunk c+1 (empty on last iteration)
    }
    __syncthreads();

    // ---- epilogue ----
    const int erow0 = wm * 32 + (lane >> 2);
    const int ecol0 = wn * 32 + (lane & 3) * 2;

    if (mode == 0) {
        #pragma unroll
        for (int mt = 0; mt < 2; mt++)
            #pragma unroll
            for (int nt = 0; nt < 4; nt++) {
                int col = ecol0 + nt * 8;
                #pragma unroll
                for (int hlf = 0; hlf < 2; hlf++) {
                    int row = erow0 + mt * 16 + hlf * 8;
                    float2 vr, vi;
                    vr.x = to_tf32(accR[mt][nt][hlf * 2 + 0]);
                    vr.y = to_tf32(accR[mt][nt][hlf * 2 + 1]);
                    vi.x = to_tf32(accI[mt][nt][hlf * 2 + 0]);
                    vi.y = to_tf32(accI[mt][nt][hlf * 2 + 1]);
                    *(float2*)(smem + 0 * PLANE_T + row * PITCH_T + col * 4) = vr;
                    *(float2*)(smem + 1 * PLANE_T + row * PITCH_T + col * 4) = vi;
                }
            }
        __syncthreads();

        float* Td[2];
        size_t tb0 = ((size_t)b * FP + f0) * NN + n0;
        Td[0] = gTr + tb0; Td[1] = gTi + tb0;
        #pragma unroll
        for (int v = 0; v < 2; v++) {
            #pragma unroll
            for (int it = 0; it < 8; it++) {
                int slot = it * 256 + t;
                int row = slot >> 4, c4 = slot & 15;
                uint4 val = *(uint4*)(smem + v * PLANE_T + row * PITCH_T + c4 * 16);
                *(uint4*)(Td[v] + (size_t)row * NN + c4 * 4) = val;
            }
        }
    } else {
        #pragma unroll
        for (int mt = 0; mt < 2; mt++)
            #pragma unroll
            for (int nt = 0; nt < 4; nt++) {
                int col = ecol0 + nt * 8;
                #pragma unroll
                for (int hlf = 0; hlf < 2; hlf++) {
                    int row = erow0 + mt * 16 + hlf * 8;
                    float4 v4;
                    v4.x = accR[mt][nt][hlf * 2 + 0];
                    v4.y = accI[mt][nt][hlf * 2 + 0];
                    v4.z = accR[mt][nt][hlf * 2 + 1];
                    v4.w = accI[mt][nt][hlf * 2 + 1];
                    *(float4*)(smem + row * PITCH_O + col * 8) = v4;
                }
            }
        __syncthreads();

        const size_t obase = (size_t)b * FF;
        #pragma unroll 4
        for (int it = 0; it < 32; it++) {
            int slot = it * 256 + t;
            int row = slot >> 6, cc = slot & 63;
            int fr = f0 + row, gc = n0 + cc;
            if (fr < FF && gc < FF) {
                float2 v = *(float2*)(smem + row * PITCH_O + cc * 8);
                out[(obase + fr) * FF + gc] = v;
            }
        }
        if (tg >= 2 * tf + 2) {   // off-band: mirror conj-transpose
            #pragma unroll 4
            for (int it = 0; it < 32; it++) {
                int slot = it * 256 + t;
                int g = slot >> 7, ff = slot & 127;
                int gr = n0 + g, fc = f0 + ff;
                if (gr < FF && fc < FF) {
                    float2 v = *(float2*)(smem + ff * PITCH_O + g * 8);
                    out[(obase + gr) * FF + fc] = make_float2(v.x, -v.y);
                }
            }
        }
    }
}

// ---------------------------------------------------------------------------
extern "C" void kernel_launch(void* const* d_in, const int* in_sizes, int n_in,
                              void* d_out, int out_size) {
    const float* rho_re = (const float*)d_in[0];
    const float* rho_im = (const float*)d_in[1];
    const float* U_re   = (const float*)d_in[2];
    const float* U_im   = (const float*)d_in[3];
    float2* out = (float2*)d_out;

    cudaFuncSetAttribute(gemm_kernel, cudaFuncAttributeMaxDynamicSharedMemorySize, SMEM_DYN);

    amp_kernel<<<FP, 256>>>(U_re, U_im);

    dim3 hg(HT * (HT + 1) / 2, BB);
    herm_kernel<<<hg, 256>>>(rho_re, rho_im);

    dim3 g1(NN / BN, NROWT, BB);
    gemm_kernel<<<g1, 256, SMEM_DYN>>>(0, nullptr);

    dim3 g2(NPAIR2, BB);
    gemm_kernel<<<g2, 256, SMEM_DYN>>>(1, out);
}